// round 14
// baseline (speedup 1.0000x reference)
#include <cuda_runtime.h>
#include <cuda_bf16.h>
#include <cstdint>
#include <cstddef>

#define DIM 4096
#define NELEM (DIM * DIM)

// ---------------- device scratch (no allocs allowed) ----------------
__device__ float g_pmin[5120];          // [0,1024) x partials, [1024,5120) w partials
__device__ float g_pmax[5120];
__device__ float g_wrsum[DIM];
__device__ float g_scalars[8];          // 0 zero_act, 1 scale_act, 2 zero_w, 3 scale_w, 4 sa*sw, 5 za+4sa
__device__ int8_t g_xq[NELEM];
__device__ int8_t g_wq[NELEM];

// ---------------- helpers ----------------
__device__ __forceinline__ uint32_t smem_u32(const void* p) {
    uint32_t a;
    asm("{ .reg .u64 t; cvta.to.shared.u64 t, %1; cvt.u32.u64 %0, t; }" : "=r"(a) : "l"(p));
    return a;
}
__device__ __forceinline__ void cp16(uint32_t s, const void* g) {
    asm volatile("cp.async.cg.shared.global [%0], [%1], 16;" :: "r"(s), "l"(g));
}
__device__ __forceinline__ void ldsm_x4(uint32_t* r, uint32_t addr) {
    asm volatile("ldmatrix.sync.aligned.m8n8.x4.shared.b16 {%0,%1,%2,%3}, [%4];"
                 : "=r"(r[0]), "=r"(r[1]), "=r"(r[2]), "=r"(r[3]) : "r"(addr));
}
__device__ __forceinline__ void imma(int* c, const uint32_t* a, const uint32_t* b) {
    asm volatile(
        "mma.sync.aligned.m16n8k32.row.col.s32.s8.s8.s32 "
        "{%0,%1,%2,%3}, {%4,%5,%6,%7}, {%8,%9}, {%0,%1,%2,%3};"
        : "+r"(c[0]), "+r"(c[1]), "+r"(c[2]), "+r"(c[3])
        : "r"(a[0]), "r"(a[1]), "r"(a[2]), "r"(a[3]), "r"(b[0]), "r"(b[1]));
}
__device__ __forceinline__ int4 lds128v(uint32_t addr) {
    int4 v;
    asm("ld.shared.v4.b32 {%0,%1,%2,%3}, [%4];"
        : "=r"(v.x), "=r"(v.y), "=r"(v.z), "=r"(v.w) : "r"(addr));
    return v;
}
__device__ __forceinline__ int2 lds64v(uint32_t addr) {
    int2 v;
    asm("ld.shared.v2.b32 {%0,%1}, [%2];" : "=r"(v.x), "=r"(v.y) : "r"(addr));
    return v;
}
__device__ __forceinline__ void barx(int id) {
    asm volatile("bar.sync %0, 512;" :: "r"(id) : "memory");
}

// ---------------- pass 1 (fused): x min/max partials + weight row stats ----------------
__global__ void __launch_bounds__(256) k_stats(const float* __restrict__ x,
                                               const float* __restrict__ wt) {
    int tid = threadIdx.x;
    int w = tid >> 5;
    __shared__ float s0[8], s1[8], s2[8];
    if (blockIdx.x < 1024) {
        const float4* x4 = reinterpret_cast<const float4*>(x);
        int t = blockIdx.x * 256 + tid;
        float mn = 3.4e38f, mx = -3.4e38f;
#pragma unroll
        for (int i = 0; i < 16; i++) {
            float4 v = x4[t + i * (1024 * 256)];
            mn = fminf(mn, fminf(fminf(v.x, v.y), fminf(v.z, v.w)));
            mx = fmaxf(mx, fmaxf(fmaxf(v.x, v.y), fmaxf(v.z, v.w)));
        }
#pragma unroll
        for (int o = 16; o > 0; o >>= 1) {
            mn = fminf(mn, __shfl_xor_sync(0xffffffffu, mn, o));
            mx = fmaxf(mx, __shfl_xor_sync(0xffffffffu, mx, o));
        }
        if ((tid & 31) == 0) { s0[w] = mn; s1[w] = mx; }
        __syncthreads();
        if (tid == 0) {
            for (int i = 1; i < 8; i++) { mn = fminf(mn, s0[i]); mx = fmaxf(mx, s1[i]); }
            g_pmin[blockIdx.x] = mn;
            g_pmax[blockIdx.x] = mx;
        }
    } else {
        int row = blockIdx.x - 1024;
        const float4* w4 = reinterpret_cast<const float4*>(wt + (size_t)row * DIM);
        float s = 0.f, mn = 3.4e38f, mx = -3.4e38f;
#pragma unroll
        for (int i = 0; i < 4; i++) {
            float4 v = w4[tid + i * 256];
            s += (v.x + v.y) + (v.z + v.w);
            mn = fminf(mn, fminf(fminf(v.x, v.y), fminf(v.z, v.w)));
            mx = fmaxf(mx, fmaxf(fmaxf(v.x, v.y), fmaxf(v.z, v.w)));
        }
#pragma unroll
        for (int o = 16; o > 0; o >>= 1) {
            s += __shfl_xor_sync(0xffffffffu, s, o);
            mn = fminf(mn, __shfl_xor_sync(0xffffffffu, mn, o));
            mx = fmaxf(mx, __shfl_xor_sync(0xffffffffu, mx, o));
        }
        if ((tid & 31) == 0) { s0[w] = mn; s1[w] = mx; s2[w] = s; }
        __syncthreads();
        if (tid == 0) {
            for (int i = 1; i < 8; i++) {
                mn = fminf(mn, s0[i]); mx = fmaxf(mx, s1[i]); s += s2[i];
            }
            g_wrsum[row] = s;
            g_pmin[1024 + row] = mn;
            g_pmax[1024 + row] = mx;
        }
    }
}

// ---------------- pass 2: finalize scalars ----------------
__global__ void __launch_bounds__(256) k_scalars() {
    int tid = threadIdx.x;
    float xmn = 3.4e38f, xmx = -3.4e38f, wmn = 3.4e38f, wmx = -3.4e38f;
    for (int i = tid; i < 1024; i += 256) {
        xmn = fminf(xmn, g_pmin[i]); xmx = fmaxf(xmx, g_pmax[i]);
    }
    for (int i = tid; i < 4096; i += 256) {
        wmn = fminf(wmn, g_pmin[1024 + i]); wmx = fmaxf(wmx, g_pmax[1024 + i]);
    }
#pragma unroll
    for (int o = 16; o > 0; o >>= 1) {
        xmn = fminf(xmn, __shfl_xor_sync(0xffffffffu, xmn, o));
        xmx = fmaxf(xmx, __shfl_xor_sync(0xffffffffu, xmx, o));
        wmn = fminf(wmn, __shfl_xor_sync(0xffffffffu, wmn, o));
        wmx = fmaxf(wmx, __shfl_xor_sync(0xffffffffu, wmx, o));
    }
    __shared__ float s0[8], s1[8], s2[8], s3[8];
    int w = tid >> 5;
    if ((tid & 31) == 0) { s0[w] = xmn; s1[w] = xmx; s2[w] = wmn; s3[w] = wmx; }
    __syncthreads();
    if (tid == 0) {
        for (int i = 1; i < 8; i++) {
            xmn = fminf(xmn, s0[i]); xmx = fmaxf(xmx, s1[i]);
            wmn = fminf(wmn, s2[i]); wmx = fmaxf(wmx, s3[i]);
        }
        float za = xmn;
        float sa = (xmx - xmn) * 0.125f;   // /(2*HALF_RANGE) = /8 (exact)
        float sw = (wmx - wmn) * 0.125f;
        g_scalars[0] = za;
        g_scalars[1] = sa;
        g_scalars[2] = wmn;
        g_scalars[3] = sw;
        g_scalars[4] = sa * sw;
        g_scalars[5] = za + 4.0f * sa;
    }
}

// ---------------- pass 3: quantize x and w to int8 ----------------
__global__ void __launch_bounds__(256) k_quant(const float* __restrict__ x,
                                               const float* __restrict__ wt) {
    float za = g_scalars[0], sa = g_scalars[1];
    float zw = g_scalars[2], sw = g_scalars[3];
    int t = blockIdx.x * 256 + threadIdx.x;
#pragma unroll
    for (int it = 0; it < 8; it++) {
        int i = t + it * 1048576;
        const float4* src;
        int8_t* dst;
        float z, sc;
        int li;
        if (i < NELEM / 4) {
            src = reinterpret_cast<const float4*>(x); dst = g_xq; z = za; sc = sa; li = i;
        } else {
            src = reinterpret_cast<const float4*>(wt); dst = g_wq; z = zw; sc = sw; li = i - NELEM / 4;
        }
        float4 v = src[li];
        int q0 = (int)fminf(fmaxf((v.x - z) / sc - 4.0f, -4.0f), 3.0f);
        int q1 = (int)fminf(fmaxf((v.y - z) / sc - 4.0f, -4.0f), 3.0f);
        int q2 = (int)fminf(fmaxf((v.z - z) / sc - 4.0f, -4.0f), 3.0f);
        int q3 = (int)fminf(fmaxf((v.w - z) / sc - 4.0f, -4.0f), 3.0f);
        uint32_t pk = (uint32_t)(q0 & 0xFF) | ((uint32_t)(q1 & 0xFF) << 8) |
                      ((uint32_t)(q2 & 0xFF) << 16) | ((uint32_t)(q3 & 0xFF) << 24);
        *reinterpret_cast<uint32_t*>(dst + (size_t)li * 4) = pk;
    }
}

// ---------------- pass 4: dual-pipeline IMMA + DP4A GEMM, 32 warps ----------------
// 128x128 CTA tile, 1024 threads. Two INDEPENDENT 16-warp pipelines (own smem
// triple-buffer, own cp.async stream, own 512-thread named barrier):
//   group I (warps 0-15):  IMMA, 4x4 warp grid of 32x32 tiles, k [0, 1536)
//   group D (warps 16-31): DP4A, 4x4 warp grid of 32x32 tiles, k [1536, 4096)
// Now 4 warps/SMSP feed EACH pipe: imma rt 117 -> ~62 (r3-measured 4-warp rate),
// dp4a gets 4-warp latency coverage toward its rt~1 issue floor. Split 12/20
// chunks matches the per-chunk SMSP costs (7.9k vs 4.1k cyc).
#define STAGES 3
#define TILE_BYTES 16384           // 128 rows x 128B
#define STAGE_BYTES 32768          // A tile + B tile
#define GROUP_SMEM (STAGES * STAGE_BYTES)   // 96KB per group
#define GSMEM (2 * GROUP_SMEM)              // 192KB
#define NCH_I 12                   // imma chunks of 128B (k 0..1536)
#define NCH_D 20                   // dp4a chunks of 128B (k 1536..4096)
#define NTHREADS 1024

__global__ void __launch_bounds__(NTHREADS) k_gemm(const float* __restrict__ bias,
                                                   float* __restrict__ out) {
    extern __shared__ char dsm[];
    int tid = threadIdx.x;
    int wid = tid >> 5, lid = tid & 31;
    int n0 = blockIdx.x * 128, m0 = blockIdx.y * 128;
    bool is_imma = (wid < 16);
    int w16 = wid & 15;
    int warpM = w16 & 3, warpN = w16 >> 2;   // 4x4 warps, 32m x 32n tile each
    int gidx = is_imma ? 0 : 1;
    int barid = 1 + gidx;
    int tg = tid & 511;                      // thread id within group

    uint32_t gbase = smem_u32(dsm) + (uint32_t)(gidx * GROUP_SMEM);
    int kbase = is_imma ? 0 : NCH_I * 128;
    int nch = is_imma ? NCH_I : NCH_D;

    const int8_t* gA = g_xq + (size_t)m0 * DIM + kbase;
    const int8_t* gB = g_wq + (size_t)n0 * DIM + kbase;

    // cp.async mapping: 1024 16B segments per 16KB tile, 2 per thread (512 thr).
    uint32_t soff[2];
    uint32_t goff[2];
#pragma unroll
    for (int j = 0; j < 2; j++) {
        int seg = tg + j * 512;
        int row = seg >> 3, c = seg & 7;
        soff[j] = (uint32_t)(row * 128 + ((c ^ (row & 7)) << 4));
        goff[j] = (uint32_t)(row * DIM + c * 16);
    }

    // IMMA ldmatrix addressing (s8 fragments via b16 ldmatrix reinterpretation).
    uint32_t a_rowoff[2], a_rowx[2];
#pragma unroll
    for (int mt = 0; mt < 2; mt++) {
        int r = warpM * 32 + mt * 16 + ((lid >> 3) & 1) * 8 + (lid & 7);
        a_rowoff[mt] = (uint32_t)(r * 128);
        a_rowx[mt] = (uint32_t)(r & 7);
    }
    int a_khalf = (lid >> 4) & 1;
    uint32_t b_rowoff[2], b_rowx[2];
#pragma unroll
    for (int np = 0; np < 2; np++) {
        int r = warpN * 32 + np * 16 + ((lid >> 4) & 1) * 8 + (lid & 7);
        b_rowoff[np] = (uint32_t)(r * 128);
        b_rowx[np] = (uint32_t)(r & 7);
    }
    int b_khalf = (lid >> 3) & 1;

    // DP4A mapping (32x32 tile): rows warpM*32 + la + 4*ii (ii<8),
    // cols warpN*32 + lg + 8*jj (jj<4). Conflict-free broadcast on both.
    int la = lid & 3, lg = lid >> 2;

    int acc[32];
#pragma unroll
    for (int c = 0; c < 32; c++) acc[c] = 0;

    // prologue: fill STAGES-1 stages of this group's buffer
#pragma unroll
    for (int s = 0; s < STAGES - 1; s++) {
        uint32_t base = gbase + s * STAGE_BYTES;
        int ko = s * 128;
#pragma unroll
        for (int j = 0; j < 2; j++) cp16(base + soff[j], gA + goff[j] + ko);
#pragma unroll
        for (int j = 0; j < 2; j++) cp16(base + TILE_BYTES + soff[j], gB + goff[j] + ko);
        asm volatile("cp.async.commit_group;" ::: "memory");
    }

    for (int i = 0; i < nch; i++) {
        asm volatile("cp.async.wait_group %0;" :: "n"(STAGES - 2) : "memory");
        barx(barid);

        int nj = i + STAGES - 1;
        if (nj < nch) {
            uint32_t wbase = gbase + (nj % STAGES) * STAGE_BYTES;
            int ko = nj * 128;
#pragma unroll
            for (int j = 0; j < 2; j++) cp16(wbase + soff[j], gA + goff[j] + ko);
#pragma unroll
            for (int j = 0; j < 2; j++) cp16(wbase + TILE_BYTES + soff[j], gB + goff[j] + ko);
        }
        asm volatile("cp.async.commit_group;" ::: "memory");

        uint32_t baseA = gbase + (i % STAGES) * STAGE_BYTES;
        uint32_t baseB = baseA + TILE_BYTES;

        if (is_imma) {
            // 4 k-steps of m16n8k32 on the 32x32 warp tile (8 imma each)
#pragma unroll
            for (int k = 0; k < 4; k++) {
                uint32_t afr[2][4], bfr[2][4];
#pragma unroll
                for (int mt = 0; mt < 2; mt++) {
                    uint32_t col = (uint32_t)(2 * k + a_khalf) ^ a_rowx[mt];
                    ldsm_x4(afr[mt], baseA + a_rowoff[mt] + (col << 4));
                }
#pragma unroll
                for (int np = 0; np < 2; np++) {
                    uint32_t col = (uint32_t)(2 * k + b_khalf) ^ b_rowx[np];
                    ldsm_x4(bfr[np], baseB + b_rowoff[np] + (col << 4));
                }
#pragma unroll
                for (int mt = 0; mt < 2; mt++)
#pragma unroll
                    for (int np = 0; np < 2; np++)
#pragma unroll
                        for (int h = 0; h < 2; h++)
                            imma(&acc[(mt * 4 + np * 2 + h) * 4], afr[mt], bfr[np] + 2 * h);
            }
        } else {
            // 8 column-blocks of 16B on the 32x32 warp tile; B held full (4
            // lds128), A streamed 2 lds128 at a time to bound live registers.
#pragma unroll
            for (int cb = 0; cb < 8; cb++) {
                uint32_t c16 = (uint32_t)cb;
                uint32_t colB  = (c16 ^ (uint32_t)lg) << 4;
                uint32_t colA0 = (c16 ^ (uint32_t)la) << 4;
                uint32_t colA1 = (c16 ^ (uint32_t)(la + 4)) << 4;
                int4 breg[4];
#pragma unroll
                for (int jj = 0; jj < 4; jj++) {
                    int r = warpN * 32 + lg + 8 * jj;
                    breg[jj] = lds128v(baseB + (uint32_t)(r * 128) + colB);
                }
#pragma unroll
                for (int par = 0; par < 2; par++) {
                    uint32_t colA = par ? colA1 : colA0;
#pragma unroll
                    for (int t2h = 0; t2h < 2; t2h++) {
                        int4 areg[2];
#pragma unroll
                        for (int t2 = 0; t2 < 2; t2++) {
                            int r = warpM * 32 + la + 4 * (par + 2 * (t2h * 2 + t2));
                            areg[t2] = lds128v(baseA + (uint32_t)(r * 128) + colA);
                        }
#pragma unroll
                        for (int comp = 0; comp < 4; comp++)
#pragma unroll
                            for (int t2 = 0; t2 < 2; t2++) {
                                int ii = par + 2 * (t2h * 2 + t2);
                                int av = (&areg[t2].x)[comp];
#pragma unroll
                                for (int jj = 0; jj < 4; jj++)
                                    acc[ii * 4 + jj] = __dp4a(av, (&breg[jj].x)[comp],
                                                              acc[ii * 4 + jj]);
                            }
                    }
                }
            }
        }
    }

    // combine dp4a partials into imma warps, then dequant epilogue
    __syncthreads();
    int* buf = reinterpret_cast<int*>(dsm);    // 64KB, reuses pipeline stages
    if (!is_imma) {
#pragma unroll
        for (int ii = 0; ii < 8; ii++) {
            int rl = warpM * 32 + la + 4 * ii;
#pragma unroll
            for (int jj = 0; jj < 4; jj++)
                buf[rl * 128 + warpN * 32 + lg + 8 * jj] = acc[ii * 4 + jj];
        }
    }
    __syncthreads();

    if (is_imma) {
        float comb = g_scalars[4];
        float shc  = g_scalars[5];
#pragma unroll
        for (int mt = 0; mt < 2; mt++) {
            int r0l = warpM * 32 + mt * 16 + (lid >> 2);
            int r1l = r0l + 8;
            int r0 = m0 + r0l, r1 = m0 + r1l;
            float sh0 = shc * g_wrsum[r0];
            float sh1 = shc * g_wrsum[r1];
#pragma unroll
            for (int nb = 0; nb < 4; nb++) {
                int cl = warpN * 32 + nb * 8 + (lid & 3) * 2;
                int col = n0 + cl;
                float b0 = bias[col], b1 = bias[col + 1];
                int2 p0 = *reinterpret_cast<int2*>(buf + r0l * 128 + cl);
                int2 p1 = *reinterpret_cast<int2*>(buf + r1l * 128 + cl);
                const int* ac = &acc[(mt * 4 + nb) * 4];
                float2 o0, o1;
                o0.x = ((float)(ac[0] + p0.x) + b0) * comb + sh0;
                o0.y = ((float)(ac[1] + p0.y) + b1) * comb + sh0;
                o1.x = ((float)(ac[2] + p1.x) + b0) * comb + sh1;
                o1.y = ((float)(ac[3] + p1.y) + b1) * comb + sh1;
                *reinterpret_cast<float2*>(out + (size_t)r0 * DIM + col) = o0;
                *reinterpret_cast<float2*>(out + (size_t)r1 * DIM + col) = o1;
            }
        }
    }
}

// ---------------- launch ----------------
extern "C" void kernel_launch(void* const* d_in, const int* in_sizes, int n_in,
                              void* d_out, int out_size) {
    const float* x    = (const float*)d_in[0];
    const float* wt   = (const float*)d_in[1];
    const float* bias = (const float*)d_in[2];
    float* out = (float*)d_out;

    cudaFuncSetAttribute(k_gemm, cudaFuncAttributeMaxDynamicSharedMemorySize, GSMEM);

    k_stats<<<5120, 256>>>(x, wt);
    k_scalars<<<1, 256>>>();
    k_quant<<<4096, 256>>>(x, wt);
    dim3 grid(DIM / 128, DIM / 128);
    k_gemm<<<grid, NTHREADS, GSMEM>>>(bias, out);
}

// round 15
// speedup vs baseline: 1.3854x; 1.3854x over previous
#include <cuda_runtime.h>
#include <cuda_bf16.h>
#include <cstdint>
#include <cstddef>

#define DIM 4096
#define NELEM (DIM * DIM)

// ---------------- device scratch (no allocs allowed) ----------------
__device__ float g_pmin[5120];          // [0,1024) x partials, [1024,5120) w partials
__device__ float g_pmax[5120];
__device__ float g_wrsum[DIM];
__device__ float g_scalars[8];          // 0 zero_act, 1 scale_act, 2 zero_w, 3 scale_w, 4 sa*sw, 5 za+4sa
__device__ int8_t g_xq[NELEM];
__device__ int8_t g_wq[NELEM];

// ---------------- helpers ----------------
__device__ __forceinline__ uint32_t smem_u32(const void* p) {
    uint32_t a;
    asm("{ .reg .u64 t; cvta.to.shared.u64 t, %1; cvt.u32.u64 %0, t; }" : "=r"(a) : "l"(p));
    return a;
}
__device__ __forceinline__ void cp16(uint32_t s, const void* g) {
    asm volatile("cp.async.cg.shared.global [%0], [%1], 16;" :: "r"(s), "l"(g));
}
__device__ __forceinline__ void ldsm_x4(uint32_t* r, uint32_t addr) {
    asm volatile("ldmatrix.sync.aligned.m8n8.x4.shared.b16 {%0,%1,%2,%3}, [%4];"
                 : "=r"(r[0]), "=r"(r[1]), "=r"(r[2]), "=r"(r[3]) : "r"(addr));
}
__device__ __forceinline__ void imma(int* c, const uint32_t* a, const uint32_t* b) {
    asm volatile(
        "mma.sync.aligned.m16n8k32.row.col.s32.s8.s8.s32 "
        "{%0,%1,%2,%3}, {%4,%5,%6,%7}, {%8,%9}, {%0,%1,%2,%3};"
        : "+r"(c[0]), "+r"(c[1]), "+r"(c[2]), "+r"(c[3])
        : "r"(a[0]), "r"(a[1]), "r"(a[2]), "r"(a[3]), "r"(b[0]), "r"(b[1]));
}
__device__ __forceinline__ int4 lds128v(uint32_t addr) {
    int4 v;
    asm("ld.shared.v4.b32 {%0,%1,%2,%3}, [%4];"
        : "=r"(v.x), "=r"(v.y), "=r"(v.z), "=r"(v.w) : "r"(addr));
    return v;
}
__device__ __forceinline__ void barx(int id) {
    asm volatile("bar.sync %0, 256;" :: "r"(id) : "memory");
}

// ---------------- pass 1 (fused): x min/max partials + weight row stats ----------------
__global__ void __launch_bounds__(256) k_stats(const float* __restrict__ x,
                                               const float* __restrict__ wt) {
    int tid = threadIdx.x;
    int w = tid >> 5;
    __shared__ float s0[8], s1[8], s2[8];
    if (blockIdx.x < 1024) {
        const float4* x4 = reinterpret_cast<const float4*>(x);
        int t = blockIdx.x * 256 + tid;
        float mn = 3.4e38f, mx = -3.4e38f;
#pragma unroll
        for (int i = 0; i < 16; i++) {
            float4 v = x4[t + i * (1024 * 256)];
            mn = fminf(mn, fminf(fminf(v.x, v.y), fminf(v.z, v.w)));
            mx = fmaxf(mx, fmaxf(fmaxf(v.x, v.y), fmaxf(v.z, v.w)));
        }
#pragma unroll
        for (int o = 16; o > 0; o >>= 1) {
            mn = fminf(mn, __shfl_xor_sync(0xffffffffu, mn, o));
            mx = fmaxf(mx, __shfl_xor_sync(0xffffffffu, mx, o));
        }
        if ((tid & 31) == 0) { s0[w] = mn; s1[w] = mx; }
        __syncthreads();
        if (tid == 0) {
            for (int i = 1; i < 8; i++) { mn = fminf(mn, s0[i]); mx = fmaxf(mx, s1[i]); }
            g_pmin[blockIdx.x] = mn;
            g_pmax[blockIdx.x] = mx;
        }
    } else {
        int row = blockIdx.x - 1024;
        const float4* w4 = reinterpret_cast<const float4*>(wt + (size_t)row * DIM);
        float s = 0.f, mn = 3.4e38f, mx = -3.4e38f;
#pragma unroll
        for (int i = 0; i < 4; i++) {
            float4 v = w4[tid + i * 256];
            s += (v.x + v.y) + (v.z + v.w);
            mn = fminf(mn, fminf(fminf(v.x, v.y), fminf(v.z, v.w)));
            mx = fmaxf(mx, fmaxf(fmaxf(v.x, v.y), fmaxf(v.z, v.w)));
        }
#pragma unroll
        for (int o = 16; o > 0; o >>= 1) {
            s += __shfl_xor_sync(0xffffffffu, s, o);
            mn = fminf(mn, __shfl_xor_sync(0xffffffffu, mn, o));
            mx = fmaxf(mx, __shfl_xor_sync(0xffffffffu, mx, o));
        }
        if ((tid & 31) == 0) { s0[w] = mn; s1[w] = mx; s2[w] = s; }
        __syncthreads();
        if (tid == 0) {
            for (int i = 1; i < 8; i++) {
                mn = fminf(mn, s0[i]); mx = fmaxf(mx, s1[i]); s += s2[i];
            }
            g_wrsum[row] = s;
            g_pmin[1024 + row] = mn;
            g_pmax[1024 + row] = mx;
        }
    }
}

// ---------------- pass 2: finalize scalars ----------------
__global__ void __launch_bounds__(256) k_scalars() {
    int tid = threadIdx.x;
    float xmn = 3.4e38f, xmx = -3.4e38f, wmn = 3.4e38f, wmx = -3.4e38f;
    for (int i = tid; i < 1024; i += 256) {
        xmn = fminf(xmn, g_pmin[i]); xmx = fmaxf(xmx, g_pmax[i]);
    }
    for (int i = tid; i < 4096; i += 256) {
        wmn = fminf(wmn, g_pmin[1024 + i]); wmx = fmaxf(wmx, g_pmax[1024 + i]);
    }
#pragma unroll
    for (int o = 16; o > 0; o >>= 1) {
        xmn = fminf(xmn, __shfl_xor_sync(0xffffffffu, xmn, o));
        xmx = fmaxf(xmx, __shfl_xor_sync(0xffffffffu, xmx, o));
        wmn = fminf(wmn, __shfl_xor_sync(0xffffffffu, wmn, o));
        wmx = fmaxf(wmx, __shfl_xor_sync(0xffffffffu, wmx, o));
    }
    __shared__ float s0[8], s1[8], s2[8], s3[8];
    int w = tid >> 5;
    if ((tid & 31) == 0) { s0[w] = xmn; s1[w] = xmx; s2[w] = wmn; s3[w] = wmx; }
    __syncthreads();
    if (tid == 0) {
        for (int i = 1; i < 8; i++) {
            xmn = fminf(xmn, s0[i]); xmx = fmaxf(xmx, s1[i]);
            wmn = fminf(wmn, s2[i]); wmx = fmaxf(wmx, s3[i]);
        }
        float za = xmn;
        float sa = (xmx - xmn) * 0.125f;   // /(2*HALF_RANGE) = /8 (exact)
        float sw = (wmx - wmn) * 0.125f;
        g_scalars[0] = za;
        g_scalars[1] = sa;
        g_scalars[2] = wmn;
        g_scalars[3] = sw;
        g_scalars[4] = sa * sw;
        g_scalars[5] = za + 4.0f * sa;
    }
}

// ---------------- pass 3: quantize x and w to int8 ----------------
__global__ void __launch_bounds__(256) k_quant(const float* __restrict__ x,
                                               const float* __restrict__ wt) {
    float za = g_scalars[0], sa = g_scalars[1];
    float zw = g_scalars[2], sw = g_scalars[3];
    int t = blockIdx.x * 256 + threadIdx.x;
#pragma unroll
    for (int it = 0; it < 8; it++) {
        int i = t + it * 1048576;
        const float4* src;
        int8_t* dst;
        float z, sc;
        int li;
        if (i < NELEM / 4) {
            src = reinterpret_cast<const float4*>(x); dst = g_xq; z = za; sc = sa; li = i;
        } else {
            src = reinterpret_cast<const float4*>(wt); dst = g_wq; z = zw; sc = sw; li = i - NELEM / 4;
        }
        float4 v = src[li];
        int q0 = (int)fminf(fmaxf((v.x - z) / sc - 4.0f, -4.0f), 3.0f);
        int q1 = (int)fminf(fmaxf((v.y - z) / sc - 4.0f, -4.0f), 3.0f);
        int q2 = (int)fminf(fmaxf((v.z - z) / sc - 4.0f, -4.0f), 3.0f);
        int q3 = (int)fminf(fmaxf((v.w - z) / sc - 4.0f, -4.0f), 3.0f);
        uint32_t pk = (uint32_t)(q0 & 0xFF) | ((uint32_t)(q1 & 0xFF) << 8) |
                      ((uint32_t)(q2 & 0xFF) << 16) | ((uint32_t)(q3 & 0xFF) << 24);
        *reinterpret_cast<uint32_t*>(dst + (size_t)li * 4) = pk;
    }
}

// ---------------- pass 4: dual-pipeline DP4A + IMMA GEMM + dequant epilogue ----------------
// 128x128 CTA tile, 512 threads. Two INDEPENDENT 8-warp pipelines (own 96KB
// smem triple-buffer, own cp.async stream, own named barrier; no __syncthreads
// in the mainloop). ROLE ASSIGNMENT EXPLOITS THE HI-WID-FIRST ARBITER:
//   group D (warps 0-7,  LOW  priority): DP4A (fma pipe), k [2048, 4096)
//   group I (warps 8-15, HIGH priority): IMMA (tensor pipe), k [0, 2048)
// The imma warps' sparse ldsm/imma issues now preempt the issue-hungry dp4a
// warps instead of being starved by them -> tensor pipe fills its idle 28%.
// dp4a has ~2x slack to its own floor and absorbs the yielded slots.
#define STAGES 3
#define TILE_BYTES 16384           // 128 rows x 128B
#define STAGE_BYTES 32768          // A tile + B tile
#define GROUP_SMEM (STAGES * STAGE_BYTES)   // 96KB per group
#define GSMEM (2 * GROUP_SMEM)              // 192KB
#define NCH 16                     // chunks of 128B per group
#define NTHREADS 512

__global__ void __launch_bounds__(NTHREADS) k_gemm(const float* __restrict__ bias,
                                                   float* __restrict__ out) {
    extern __shared__ char dsm[];
    int tid = threadIdx.x;
    int wid = tid >> 5, lid = tid & 31;
    int n0 = blockIdx.x * 128, m0 = blockIdx.y * 128;
    bool is_imma = (wid >= 8);             // HIGH-wid warps -> tensor pipe
    int w8 = wid & 7;
    int warpM = w8 & 3, warpN = w8 >> 2;   // both groups: 4x2 warps, 32m x 64n tile
    int gidx = wid >> 3;                   // physical warp-group -> smem partition
    int barid = 1 + gidx;
    int tg = tid & 255;                    // thread id within group

    uint32_t gbase = smem_u32(dsm) + (uint32_t)(gidx * GROUP_SMEM);
    int kbase = is_imma ? 0 : NCH * 128;   // imma k[0,2048), dp4a k[2048,4096)

    const int8_t* gA = g_xq + (size_t)m0 * DIM + kbase;
    const int8_t* gB = g_wq + (size_t)n0 * DIM + kbase;

    // cp.async mapping: 1024 16B segments per 16KB tile, 4 per thread (256 thr).
    uint32_t soff[4];
    uint32_t goff[4];
#pragma unroll
    for (int j = 0; j < 4; j++) {
        int seg = tg + j * 256;
        int row = seg >> 3, c = seg & 7;
        soff[j] = (uint32_t)(row * 128 + ((c ^ (row & 7)) << 4));
        goff[j] = (uint32_t)(row * DIM + c * 16);
    }

    // IMMA ldmatrix addressing (s8 fragments via b16 ldmatrix reinterpretation).
    uint32_t a_rowoff[2], a_rowx[2];
#pragma unroll
    for (int mt = 0; mt < 2; mt++) {
        int r = warpM * 32 + mt * 16 + ((lid >> 3) & 1) * 8 + (lid & 7);
        a_rowoff[mt] = (uint32_t)(r * 128);
        a_rowx[mt] = (uint32_t)(r & 7);
    }
    int a_khalf = (lid >> 4) & 1;
    uint32_t b_rowoff[4], b_rowx[4];
#pragma unroll
    for (int np = 0; np < 4; np++) {
        int r = warpN * 64 + np * 16 + ((lid >> 4) & 1) * 8 + (lid & 7);
        b_rowoff[np] = (uint32_t)(r * 128);
        b_rowx[np] = (uint32_t)(r & 7);
    }
    int b_khalf = (lid >> 3) & 1;

    // DP4A mapping: rows warpM*32 + la + 4*ii, cols warpN*64 + lg + 8*jj.
    int la = lid & 3, lg = lid >> 2;

    int acc[64];
#pragma unroll
    for (int c = 0; c < 64; c++) acc[c] = 0;

    // prologue: fill STAGES-1 stages of this group's buffer
#pragma unroll
    for (int s = 0; s < STAGES - 1; s++) {
        uint32_t base = gbase + s * STAGE_BYTES;
        int ko = s * 128;
#pragma unroll
        for (int j = 0; j < 4; j++) cp16(base + soff[j], gA + goff[j] + ko);
#pragma unroll
        for (int j = 0; j < 4; j++) cp16(base + TILE_BYTES + soff[j], gB + goff[j] + ko);
        asm volatile("cp.async.commit_group;" ::: "memory");
    }

    for (int i = 0; i < NCH; i++) {
        asm volatile("cp.async.wait_group %0;" :: "n"(STAGES - 2) : "memory");
        barx(barid);

        int nj = i + STAGES - 1;
        if (nj < NCH) {
            uint32_t wbase = gbase + (nj % STAGES) * STAGE_BYTES;
            int ko = nj * 128;
#pragma unroll
            for (int j = 0; j < 4; j++) cp16(wbase + soff[j], gA + goff[j] + ko);
#pragma unroll
            for (int j = 0; j < 4; j++) cp16(wbase + TILE_BYTES + soff[j], gB + goff[j] + ko);
        }
        asm volatile("cp.async.commit_group;" ::: "memory");

        uint32_t baseA = gbase + (i % STAGES) * STAGE_BYTES;
        uint32_t baseB = baseA + TILE_BYTES;

        if (is_imma) {
            // 4 k-steps of m16n8k32; 6 ldsm per k-step hoisted ahead of 16 immas
#pragma unroll
            for (int k = 0; k < 4; k++) {
                uint32_t afr[2][4], bfr[4][4];
#pragma unroll
                for (int mt = 0; mt < 2; mt++) {
                    uint32_t col = (uint32_t)(2 * k + a_khalf) ^ a_rowx[mt];
                    ldsm_x4(afr[mt], baseA + a_rowoff[mt] + (col << 4));
                }
#pragma unroll
                for (int np = 0; np < 4; np++) {
                    uint32_t col = (uint32_t)(2 * k + b_khalf) ^ b_rowx[np];
                    ldsm_x4(bfr[np], baseB + b_rowoff[np] + (col << 4));
                }
#pragma unroll
                for (int np = 0; np < 4; np++)
#pragma unroll
                    for (int mt = 0; mt < 2; mt++) {
                        imma(&acc[(mt * 8 + np * 2 + 0) * 4], afr[mt], bfr[np] + 0);
                        imma(&acc[(mt * 8 + np * 2 + 1) * 4], afr[mt], bfr[np] + 2);
                    }
            }
        } else {
            // 8 column-blocks of 16B; component-major dp4a (chain-free accs)
#pragma unroll
            for (int cb = 0; cb < 8; cb++) {
                uint32_t c16 = (uint32_t)cb;
                uint32_t colB  = (c16 ^ (uint32_t)lg) << 4;
                uint32_t colA0 = (c16 ^ (uint32_t)la) << 4;
                uint32_t colA1 = (c16 ^ (uint32_t)(la + 4)) << 4;
#pragma unroll
                for (int jjh = 0; jjh < 2; jjh++) {
                    int4 breg[4];
#pragma unroll
                    for (int j2 = 0; j2 < 4; j2++) {
                        int r = warpN * 64 + lg + 8 * (jjh * 4 + j2);
                        breg[j2] = lds128v(baseB + (uint32_t)(r * 128) + colB);
                    }
#pragma unroll
                    for (int par = 0; par < 2; par++) {
                        uint32_t colA = par ? colA1 : colA0;
                        int4 areg[4];
#pragma unroll
                        for (int t2 = 0; t2 < 4; t2++) {
                            int r = warpM * 32 + la + 4 * (par + 2 * t2);
                            areg[t2] = lds128v(baseA + (uint32_t)(r * 128) + colA);
                        }
#pragma unroll
                        for (int comp = 0; comp < 4; comp++) {
#pragma unroll
                            for (int t2 = 0; t2 < 4; t2++) {
                                int av = (&areg[t2].x)[comp];
                                int ii = par + 2 * t2;
#pragma unroll
                                for (int j2 = 0; j2 < 4; j2++) {
                                    int jj = jjh * 4 + j2;
                                    acc[ii * 8 + jj] = __dp4a(av, (&breg[j2].x)[comp],
                                                              acc[ii * 8 + jj]);
                                }
                            }
                        }
                    }
                }
            }
        }
    }

    // combine dp4a partials into imma warps, then dequant epilogue
    __syncthreads();
    int* buf = reinterpret_cast<int*>(dsm);    // 64KB, reuses pipeline stages
    if (!is_imma) {
#pragma unroll
        for (int ii = 0; ii < 8; ii++) {
            int rl = warpM * 32 + la + 4 * ii;
#pragma unroll
            for (int jj = 0; jj < 8; jj++)
                buf[rl * 128 + warpN * 64 + lg + 8 * jj] = acc[ii * 8 + jj];
        }
    }
    __syncthreads();

    if (is_imma) {
        float comb = g_scalars[4];
        float shc  = g_scalars[5];
#pragma unroll
        for (int mt = 0; mt < 2; mt++) {
            int r0l = warpM * 32 + mt * 16 + (lid >> 2);
            int r1l = r0l + 8;
            int r0 = m0 + r0l, r1 = m0 + r1l;
            float sh0 = shc * g_wrsum[r0];
            float sh1 = shc * g_wrsum[r1];
#pragma unroll
            for (int nt = 0; nt < 8; nt++) {
                int cl = warpN * 64 + nt * 8 + (lid & 3) * 2;
                int col = n0 + cl;
                float b0 = bias[col], b1 = bias[col + 1];
                int2 p0 = *reinterpret_cast<int2*>(buf + r0l * 128 + cl);
                int2 p1 = *reinterpret_cast<int2*>(buf + r1l * 128 + cl);
                const int* ac = &acc[(mt * 8 + nt) * 4];
                float2 o0, o1;
                o0.x = ((float)(ac[0] + p0.x) + b0) * comb + sh0;
                o0.y = ((float)(ac[1] + p0.y) + b1) * comb + sh0;
                o1.x = ((float)(ac[2] + p1.x) + b0) * comb + sh1;
                o1.y = ((float)(ac[3] + p1.y) + b1) * comb + sh1;
                *reinterpret_cast<float2*>(out + (size_t)r0 * DIM + col) = o0;
                *reinterpret_cast<float2*>(out + (size_t)r1 * DIM + col) = o1;
            }
        }
    }
}

// ---------------- launch ----------------
extern "C" void kernel_launch(void* const* d_in, const int* in_sizes, int n_in,
                              void* d_out, int out_size) {
    const float* x    = (const float*)d_in[0];
    const float* wt   = (const float*)d_in[1];
    const float* bias = (const float*)d_in[2];
    float* out = (float*)d_out;

    cudaFuncSetAttribute(k_gemm, cudaFuncAttributeMaxDynamicSharedMemorySize, GSMEM);

    k_stats<<<5120, 256>>>(x, wt);
    k_scalars<<<1, 256>>>();
    k_quant<<<4096, 256>>>(x, wt);
    dim3 grid(DIM / 128, DIM / 128);
    k_gemm<<<grid, NTHREADS, GSMEM>>>(bias, out);
}